// round 1
// baseline (speedup 1.0000x reference)
#include <cuda_runtime.h>
#include <cuda_bf16.h>
#include <math.h>
#include <stdint.h>

// Problem constants
#define BD   4
#define SD   2048
#define DD   1024
#define FD   4096
#define ED   8
#define KK   2
#define TT   (BD*SD)          // 8192 tokens
#define CC   2048             // capacity per expert
#define NA   (TT*KK)          // 16384 assignments
#define RMS_EPS 1e-6f

// ---------------- scratch (device globals; no allocation allowed) ----------
__device__ float g_tnorm[(size_t)TT * DD];            // 33.5 MB
__device__ float g_xbuf [(size_t)ED * CC * DD];       // 67 MB
__device__ float g_mid  [(size_t)ED * CC * FD];       // 268 MB
__device__ float g_ybuf [(size_t)ED * CC * DD];       // 67 MB
__device__ int   g_eidx [NA];
__device__ float g_gate [NA];
__device__ int   g_slot [NA];
__device__ float g_gk   [NA];                         // gate * keep
__device__ int   g_sinv [ED * CC];                    // slot -> assignment (-1 empty)

// ---------------- Kernel 1: RMSNorm + router logits + softmax + top-2 -----
__global__ void k_rms_router(const float* __restrict__ x,
                             const float* __restrict__ rmsw,
                             const float* __restrict__ wr)
{
    const int t = blockIdx.x;
    const int tid = threadIdx.x;             // 256 threads
    const float* xr = x + (size_t)t * DD;

    // sum of squares
    float ss = 0.f;
    for (int d = tid; d < DD; d += 256) { float v = xr[d]; ss += v * v; }
    // block reduce
    __shared__ float s_red[8];
    for (int o = 16; o > 0; o >>= 1) ss += __shfl_down_sync(0xffffffff, ss, o);
    if ((tid & 31) == 0) s_red[tid >> 5] = ss;
    __syncthreads();
    if (tid == 0) {
        float tot = 0.f;
        #pragma unroll
        for (int w = 0; w < 8; w++) tot += s_red[w];
        s_red[0] = rsqrtf(tot / (float)DD + RMS_EPS);
    }
    __syncthreads();
    const float scale = s_red[0];

    // normalize + write + router partial dots
    float acc[ED];
    #pragma unroll
    for (int e = 0; e < ED; e++) acc[e] = 0.f;
    for (int d = tid; d < DD; d += 256) {
        float h = xr[d] * scale * rmsw[d];
        g_tnorm[(size_t)t * DD + d] = h;
        const float4 w0 = *(const float4*)(wr + (size_t)d * ED);
        const float4 w1 = *(const float4*)(wr + (size_t)d * ED + 4);
        acc[0] += h * w0.x; acc[1] += h * w0.y; acc[2] += h * w0.z; acc[3] += h * w0.w;
        acc[4] += h * w1.x; acc[5] += h * w1.y; acc[6] += h * w1.z; acc[7] += h * w1.w;
    }
    __shared__ float s_r[8][ED];
    #pragma unroll
    for (int e = 0; e < ED; e++) {
        float v = acc[e];
        for (int o = 16; o > 0; o >>= 1) v += __shfl_down_sync(0xffffffff, v, o);
        if ((tid & 31) == 0) s_r[tid >> 5][e] = v;
    }
    __syncthreads();
    __shared__ float s_log[ED];
    if (tid < ED) {
        float v = 0.f;
        #pragma unroll
        for (int w = 0; w < 8; w++) v += s_r[w][tid];
        s_log[tid] = v;
    }
    __syncthreads();
    if (tid == 0) {
        float m = s_log[0];
        #pragma unroll
        for (int e = 1; e < ED; e++) m = fmaxf(m, s_log[e]);
        float p[ED]; float sum = 0.f;
        #pragma unroll
        for (int e = 0; e < ED; e++) { p[e] = __expf(s_log[e] - m); sum += p[e]; }
        const float inv = 1.f / sum;
        #pragma unroll
        for (int e = 0; e < ED; e++) p[e] *= inv;
        // top-2 (strict > => first occurrence on ties, matching lax.top_k)
        int b0 = 0; float v0 = p[0];
        #pragma unroll
        for (int e = 1; e < ED; e++) if (p[e] > v0) { v0 = p[e]; b0 = e; }
        int b1 = -1; float v1 = -1.f;
        #pragma unroll
        for (int e = 0; e < ED; e++) if (e != b0 && p[e] > v1) { v1 = p[e]; b1 = e; }
        g_eidx[2 * t + 0] = b0; g_gate[2 * t + 0] = v0;
        g_eidx[2 * t + 1] = b1; g_gate[2 * t + 1] = v1;
    }
}

// ---------------- Kernel 2: exact token-major capacity scan (1 block) ------
__global__ void k_route_scan()
{
    const int tid = threadIdx.x;             // 256 threads, chunk = 64
    for (int i = tid; i < ED * CC; i += 256) g_sinv[i] = -1;
    __syncthreads();

    const int base = tid * (NA / 256);
    int cnt[ED];
    #pragma unroll
    for (int e = 0; e < ED; e++) cnt[e] = 0;
    for (int j = 0; j < NA / 256; j++) cnt[g_eidx[base + j]]++;

    __shared__ int scnt[256][ED];
    __shared__ int spre[256][ED];
    #pragma unroll
    for (int e = 0; e < ED; e++) scnt[tid][e] = cnt[e];
    __syncthreads();
    if (tid < ED) {
        int run = 0;
        for (int i = 0; i < 256; i++) { spre[i][tid] = run; run += scnt[i][tid]; }
    }
    __syncthreads();

    int pos[ED];
    #pragma unroll
    for (int e = 0; e < ED; e++) pos[e] = spre[tid][e];
    for (int j = 0; j < NA / 256; j++) {
        const int a = base + j;
        const int e = g_eidx[a];
        const int p = pos[e]++;
        const bool keep = (p < CC);
        const int sl = e * CC + (p < CC ? p : CC - 1);
        g_slot[a] = sl;
        g_gk[a] = keep ? g_gate[a] : 0.f;
        if (keep) g_sinv[sl] = a;
    }
}

// ---------------- Kernel 3: dispatch gather --------------------------------
__global__ void k_dispatch()
{
    const int s = blockIdx.x;                // E*C slots
    const int a = g_sinv[s];
    float4* dst = (float4*)(g_xbuf + (size_t)s * DD);
    if (a < 0) {
        dst[threadIdx.x] = make_float4(0.f, 0.f, 0.f, 0.f);
    } else {
        const int tok = a >> 1;
        const float4* src = (const float4*)(g_tnorm + (size_t)tok * DD);
        dst[threadIdx.x] = src[threadIdx.x];
    }
}

// ---------------- GEMM: 128x128 tile, BK=8, 256 thr, 8x8 micro ------------
#define BM 128
#define BN 128
#define BKK 8
#define TM 8
#define TN 8

__device__ __forceinline__ float gelu_exact(float v)
{
    return 0.5f * v * (1.f + erff(v * 0.70710678118654752f));
}

template<bool GELU>
__global__ __launch_bounds__(256, 2)
void k_gemm(const float* __restrict__ A, const float* __restrict__ B,
            float* __restrict__ C, int M, int N, int Kd)
{
    const int e = blockIdx.z;
    const float* Ae = A + (size_t)e * M * Kd;
    const float* Be = B + (size_t)e * Kd * N;
    float*       Ce = C + (size_t)e * M * N;

    __shared__ float As[BKK][BM];
    __shared__ float Bs[BKK][BN];

    const int tid = threadIdx.x;
    const int tx = tid & 15;
    const int ty = tid >> 4;
    const int row0 = blockIdx.y * BM;
    const int col0 = blockIdx.x * BN;

    const int arow = tid >> 1;
    const int acol = (tid & 1) * 4;
    const int brow = tid >> 5;
    const int bcol = (tid & 31) * 4;

    float acc[TM][TN];
    #pragma unroll
    for (int i = 0; i < TM; i++)
        #pragma unroll
        for (int j = 0; j < TN; j++) acc[i][j] = 0.f;

    for (int k0 = 0; k0 < Kd; k0 += BKK) {
        const float4 av = *(const float4*)(Ae + (size_t)(row0 + arow) * Kd + k0 + acol);
        As[acol + 0][arow] = av.x;
        As[acol + 1][arow] = av.y;
        As[acol + 2][arow] = av.z;
        As[acol + 3][arow] = av.w;
        const float4 bv = *(const float4*)(Be + (size_t)(k0 + brow) * N + col0 + bcol);
        *(float4*)&Bs[brow][bcol] = bv;
        __syncthreads();

        #pragma unroll
        for (int k = 0; k < BKK; k++) {
            float a[TM], b[TN];
            #pragma unroll
            for (int i = 0; i < TM; i++) a[i] = As[k][ty * TM + i];
            #pragma unroll
            for (int j = 0; j < TN; j++) b[j] = Bs[k][tx * TN + j];
            #pragma unroll
            for (int i = 0; i < TM; i++)
                #pragma unroll
                for (int j = 0; j < TN; j++) acc[i][j] = fmaf(a[i], b[j], acc[i][j]);
        }
        __syncthreads();
    }

    #pragma unroll
    for (int i = 0; i < TM; i++) {
        float* crow = Ce + (size_t)(row0 + ty * TM + i) * N + col0 + tx * TN;
        float4 v0, v1;
        if (GELU) {
            v0 = make_float4(gelu_exact(acc[i][0]), gelu_exact(acc[i][1]),
                             gelu_exact(acc[i][2]), gelu_exact(acc[i][3]));
            v1 = make_float4(gelu_exact(acc[i][4]), gelu_exact(acc[i][5]),
                             gelu_exact(acc[i][6]), gelu_exact(acc[i][7]));
        } else {
            v0 = make_float4(acc[i][0], acc[i][1], acc[i][2], acc[i][3]);
            v1 = make_float4(acc[i][4], acc[i][5], acc[i][6], acc[i][7]);
        }
        *(float4*)(crow) = v0;
        *(float4*)(crow + 4) = v1;
    }
}

// ---------------- Kernel 6: combine ---------------------------------------
__global__ void k_combine(float* __restrict__ out)
{
    const int t = blockIdx.x;
    const int s0 = g_slot[2 * t + 0];
    const int s1 = g_slot[2 * t + 1];
    const float g0 = g_gk[2 * t + 0];
    const float g1 = g_gk[2 * t + 1];
    const float4* y0 = (const float4*)(g_ybuf + (size_t)s0 * DD);
    const float4* y1 = (const float4*)(g_ybuf + (size_t)s1 * DD);
    float4* o = (float4*)(out + (size_t)t * DD);
    const float4 a = y0[threadIdx.x];
    const float4 b = y1[threadIdx.x];
    o[threadIdx.x] = make_float4(g0 * a.x + g1 * b.x,
                                 g0 * a.y + g1 * b.y,
                                 g0 * a.z + g1 * b.z,
                                 g0 * a.w + g1 * b.w);
}

// ---------------- launch ---------------------------------------------------
extern "C" void kernel_launch(void* const* d_in, const int* in_sizes, int n_in,
                              void* d_out, int out_size)
{
    const float* x    = (const float*)d_in[0];  // [B,S,D]
    const float* rmsw = (const float*)d_in[1];  // [D]
    const float* wr   = (const float*)d_in[2];  // [D,E]
    const float* w1   = (const float*)d_in[3];  // [E,D,F]
    const float* w2   = (const float*)d_in[4];  // [E,F,D]
    float* out = (float*)d_out;

    float *tnorm_p, *xbuf_p, *mid_p, *ybuf_p;
    cudaGetSymbolAddress((void**)&tnorm_p, g_tnorm);
    cudaGetSymbolAddress((void**)&xbuf_p,  g_xbuf);
    cudaGetSymbolAddress((void**)&mid_p,   g_mid);
    cudaGetSymbolAddress((void**)&ybuf_p,  g_ybuf);
    (void)tnorm_p;

    // 1. RMSNorm + router
    k_rms_router<<<TT, 256>>>(x, rmsw, wr);
    // 2. capacity scan (exact token-major order)
    k_route_scan<<<1, 256>>>();
    // 3. dispatch
    k_dispatch<<<ED * CC, 256>>>();
    // 4. GEMM1 + GeLU:  [E] x ( [C,D] @ [D,F] )
    {
        dim3 grid(FD / BN, CC / BM, ED);
        k_gemm<true><<<grid, 256>>>(xbuf_p, w1, mid_p, CC, FD, DD);
    }
    // 5. GEMM2: [E] x ( [C,F] @ [F,D] )
    {
        dim3 grid(DD / BN, CC / BM, ED);
        k_gemm<false><<<grid, 256>>>(mid_p, w2, ybuf_p, CC, DD, FD);
    }
    // 6. combine
    k_combine<<<TT, 256>>>(out);
}

// round 3
// speedup vs baseline: 3.0492x; 3.0492x over previous
#include <cuda_runtime.h>
#include <math.h>
#include <stdint.h>

// Problem constants
#define BD   4
#define SD   2048
#define DD   1024
#define FD   4096
#define ED   8
#define KK   2
#define TT   (BD*SD)          // 8192 tokens
#define CC   2048             // capacity per expert
#define NA   (TT*KK)          // 16384 assignments
#define RMS_EPS 1e-6f

// ---------------- scratch (device globals; no allocation allowed) ----------
__device__ float g_tnorm[(size_t)TT * DD];            // 33.5 MB
__device__ float g_xbuf [(size_t)ED * CC * DD];       // 67 MB  (tf32-rounded)
__device__ float g_mid  [(size_t)ED * CC * FD];       // 268 MB (tf32-rounded)
__device__ float g_ybuf [(size_t)ED * CC * DD];       // 67 MB
__device__ float g_w1t  [(size_t)ED * DD * FD];       // 134 MB [E,F,D] tf32-rounded
__device__ float g_w2t  [(size_t)ED * DD * FD];       // 134 MB [E,D,F] tf32-rounded
__device__ int   g_eidx [NA];
__device__ float g_gate [NA];
__device__ int   g_slot [NA];
__device__ float g_gk   [NA];
__device__ int   g_sinv [ED * CC];

// ---------------- helpers ---------------------------------------------------
__device__ __forceinline__ float tf32r(float x) {
    uint32_t r;
    asm("cvt.rna.tf32.f32 %0, %1;" : "=r"(r) : "f"(x));
    return __uint_as_float(r);
}

#define CP_ASYNC16(sm, gp) \
    asm volatile("cp.async.cg.shared.global [%0], [%1], 16;" :: "r"(sm), "l"(gp) : "memory")
#define CP_COMMIT() asm volatile("cp.async.commit_group;" ::: "memory")
#define CP_WAIT1()  asm volatile("cp.async.wait_group 1;" ::: "memory")
#define CP_WAIT0()  asm volatile("cp.async.wait_group 0;" ::: "memory")

__device__ __forceinline__ uint32_t smem_u32(const void* p) {
    uint32_t a;
    asm("{ .reg .u64 t; cvta.to.shared.u64 t, %1; cvt.u32.u64 %0, t; }" : "=r"(a) : "l"(p));
    return a;
}

#define MMA_TF32(d, a, b) \
    asm volatile("mma.sync.aligned.m16n8k8.row.col.f32.tf32.tf32.f32 " \
        "{%0,%1,%2,%3}, {%4,%5,%6,%7}, {%8,%9}, {%0,%1,%2,%3};" \
        : "+f"((d)[0]), "+f"((d)[1]), "+f"((d)[2]), "+f"((d)[3]) \
        : "r"((a)[0]), "r"((a)[1]), "r"((a)[2]), "r"((a)[3]), \
          "r"((b)[0]), "r"((b)[1]))

__device__ __forceinline__ float gelu_exact(float v) {
    return 0.5f * v * (1.f + erff(v * 0.70710678118654752f));
}

// ---------------- Kernel 1: RMSNorm + router + softmax + top-2 ------------
__global__ void k_rms_router(const float* __restrict__ x,
                             const float* __restrict__ rmsw,
                             const float* __restrict__ wr)
{
    const int t = blockIdx.x;
    const int tid = threadIdx.x;             // 256 threads
    const float* xr = x + (size_t)t * DD;

    float ss = 0.f;
    for (int d = tid; d < DD; d += 256) { float v = xr[d]; ss += v * v; }
    __shared__ float s_red[8];
    for (int o = 16; o > 0; o >>= 1) ss += __shfl_down_sync(0xffffffff, ss, o);
    if ((tid & 31) == 0) s_red[tid >> 5] = ss;
    __syncthreads();
    if (tid == 0) {
        float tot = 0.f;
        #pragma unroll
        for (int w = 0; w < 8; w++) tot += s_red[w];
        s_red[0] = rsqrtf(tot / (float)DD + RMS_EPS);
    }
    __syncthreads();
    const float scale = s_red[0];

    float acc[ED];
    #pragma unroll
    for (int e = 0; e < ED; e++) acc[e] = 0.f;
    for (int d = tid; d < DD; d += 256) {
        float h = xr[d] * scale * rmsw[d];
        g_tnorm[(size_t)t * DD + d] = h;
        const float4 w0 = *(const float4*)(wr + (size_t)d * ED);
        const float4 w1 = *(const float4*)(wr + (size_t)d * ED + 4);
        acc[0] += h * w0.x; acc[1] += h * w0.y; acc[2] += h * w0.z; acc[3] += h * w0.w;
        acc[4] += h * w1.x; acc[5] += h * w1.y; acc[6] += h * w1.z; acc[7] += h * w1.w;
    }
    __shared__ float s_r[8][ED];
    #pragma unroll
    for (int e = 0; e < ED; e++) {
        float v = acc[e];
        for (int o = 16; o > 0; o >>= 1) v += __shfl_down_sync(0xffffffff, v, o);
        if ((tid & 31) == 0) s_r[tid >> 5][e] = v;
    }
    __syncthreads();
    __shared__ float s_log[ED];
    if (tid < ED) {
        float v = 0.f;
        #pragma unroll
        for (int w = 0; w < 8; w++) v += s_r[w][tid];
        s_log[tid] = v;
    }
    __syncthreads();
    if (tid == 0) {
        float m = s_log[0];
        #pragma unroll
        for (int e = 1; e < ED; e++) m = fmaxf(m, s_log[e]);
        float p[ED]; float sum = 0.f;
        #pragma unroll
        for (int e = 0; e < ED; e++) { p[e] = __expf(s_log[e] - m); sum += p[e]; }
        const float inv = 1.f / sum;
        #pragma unroll
        for (int e = 0; e < ED; e++) p[e] *= inv;
        int b0 = 0; float v0 = p[0];
        #pragma unroll
        for (int e = 1; e < ED; e++) if (p[e] > v0) { v0 = p[e]; b0 = e; }
        int b1 = -1; float v1 = -1.f;
        #pragma unroll
        for (int e = 0; e < ED; e++) if (e != b0 && p[e] > v1) { v1 = p[e]; b1 = e; }
        g_eidx[2 * t + 0] = b0; g_gate[2 * t + 0] = v0;
        g_eidx[2 * t + 1] = b1; g_gate[2 * t + 1] = v1;
    }
}

// ---------------- Kernel 2: exact token-major capacity scan (1 block) ------
__global__ void k_route_scan()
{
    const int tid = threadIdx.x;             // 256 threads
    for (int i = tid; i < ED * CC; i += 256) g_sinv[i] = -1;
    __syncthreads();

    const int base = tid * (NA / 256);
    int cnt[ED];
    #pragma unroll
    for (int e = 0; e < ED; e++) cnt[e] = 0;
    for (int j = 0; j < NA / 256; j++) cnt[g_eidx[base + j]]++;

    __shared__ int scnt[256][ED];
    __shared__ int spre[256][ED];
    #pragma unroll
    for (int e = 0; e < ED; e++) scnt[tid][e] = cnt[e];
    __syncthreads();
    if (tid < ED) {
        int run = 0;
        for (int i = 0; i < 256; i++) { spre[i][tid] = run; run += scnt[i][tid]; }
    }
    __syncthreads();

    int pos[ED];
    #pragma unroll
    for (int e = 0; e < ED; e++) pos[e] = spre[tid][e];
    for (int j = 0; j < NA / 256; j++) {
        const int a = base + j;
        const int e = g_eidx[a];
        const int p = pos[e]++;
        const bool keep = (p < CC);
        const int sl = e * CC + (p < CC ? p : CC - 1);
        g_slot[a] = sl;
        g_gk[a] = keep ? g_gate[a] : 0.f;
        if (keep) g_sinv[sl] = a;
    }
}

// ---------------- Kernel 3: dispatch gather (+ tf32 round) -----------------
__global__ void k_dispatch()
{
    const int s = blockIdx.x;                // E*C slots
    const int a = g_sinv[s];
    float4* dst = (float4*)(g_xbuf + (size_t)s * DD);
    if (a < 0) {
        dst[threadIdx.x] = make_float4(0.f, 0.f, 0.f, 0.f);
    } else {
        const int tok = a >> 1;
        const float4* src = (const float4*)(g_tnorm + (size_t)tok * DD);
        float4 v = src[threadIdx.x];
        v.x = tf32r(v.x); v.y = tf32r(v.y); v.z = tf32r(v.z); v.w = tf32r(v.w);
        dst[threadIdx.x] = v;
    }
}

// ---------------- Kernel 4: weight transpose + tf32 round ------------------
// src [e][R][C] -> dst [e][C][R]
__global__ void k_transpose_round(const float* __restrict__ src,
                                  float* __restrict__ dst, int R, int C)
{
    __shared__ float t[32][33];
    const int e = blockIdx.z;
    const float* s = src + (size_t)e * R * C;
    float* d = dst + (size_t)e * R * C;
    const int x = blockIdx.x * 32 + threadIdx.x;
    const int y0 = blockIdx.y * 32;
    #pragma unroll
    for (int j = 0; j < 4; j++)
        t[threadIdx.y + 8 * j][threadIdx.x] = s[(size_t)(y0 + threadIdx.y + 8 * j) * C + x];
    __syncthreads();
    const int x2 = y0 + threadIdx.x;
    const int y2 = blockIdx.x * 32;
    #pragma unroll
    for (int j = 0; j < 4; j++)
        d[(size_t)(y2 + threadIdx.y + 8 * j) * R + x2] = tf32r(t[threadIdx.x][threadIdx.y + 8 * j]);
}

// ---------------- Kernel 5: tf32 mma.sync GEMM -----------------------------
// A: [E, CC, Kd] K-major. B: [E, N, Kd] K-major. C[m][n] = sum_k A[m][k]*B[n][k].
// CTA tile 128x128, BK=32, 3-stage cp.async, 8 warps of 64x32.
#define BKC 32
#define AST 36                   // padded row stride in floats
#define STAGE_F (128 * AST * 2)  // floats per stage (A + B)
#define SMEMSZ (3 * STAGE_F * 4)

template<bool GELU>
__global__ void __launch_bounds__(256)
k_mmagemm(const float* __restrict__ A, const float* __restrict__ B,
          float* __restrict__ C, int N, int Kd)
{
    extern __shared__ float sm[];
    const int tid = threadIdx.x;
    const int wid = tid >> 5;
    const int lane = tid & 31;
    const int lq = lane >> 2;       // 0..7
    const int lr = lane & 3;        // 0..3
    const int wm = wid >> 2;        // 0..1 (64-row half)
    const int wn = wid & 3;         // 0..3 (32-col quarter)

    const int e = blockIdx.z;
    const int row0 = blockIdx.x * 128;
    const int col0 = blockIdx.y * 128;

    const float* Ag = A + (size_t)e * CC * Kd + (size_t)row0 * Kd;
    const float* Bg = B + (size_t)e * N * Kd + (size_t)col0 * Kd;
    float* Ce = C + (size_t)e * CC * N;

    // staging addresses: thread covers 4 A-vectors + 4 B-vectors (float4)
    // vector v (0..1023): row = v>>3, col4 = v&7
    const uint32_t sbase = smem_u32(sm);
    uint32_t sA[4], sB[4];
    const float* gA[4];
    const float* gB[4];
    #pragma unroll
    for (int j = 0; j < 4; j++) {
        const int v = tid + 256 * j;
        const int r = v >> 3, c4 = v & 7;
        sA[j] = sbase + (uint32_t)(r * AST + c4 * 4) * 4;
        sB[j] = sbase + (uint32_t)(128 * AST + r * AST + c4 * 4) * 4;
        gA[j] = Ag + (size_t)r * Kd + c4 * 4;
        gB[j] = Bg + (size_t)r * Kd + c4 * 4;
    }

    #define STAGE(chunk, buf) do { \
        const uint32_t _o = (uint32_t)(buf) * (STAGE_F * 4); \
        const int _k = (chunk) * BKC; \
        _Pragma("unroll") \
        for (int _j = 0; _j < 4; _j++) CP_ASYNC16(sA[_j] + _o, gA[_j] + _k); \
        _Pragma("unroll") \
        for (int _j = 0; _j < 4; _j++) CP_ASYNC16(sB[_j] + _o, gB[_j] + _k); \
        CP_COMMIT(); \
    } while (0)

    const int NC = Kd / BKC;
    STAGE(0, 0);
    STAGE(1, 1);

    float acc[4][4][4];
    #pragma unroll
    for (int mi = 0; mi < 4; mi++)
        #pragma unroll
        for (int ni = 0; ni < 4; ni++)
            #pragma unroll
            for (int q = 0; q < 4; q++) acc[mi][ni][q] = 0.f;

    // fragment base offsets (floats)
    const int aoff = (wm * 64 + lq) * AST + lr;
    const int boff = 128 * AST + (wn * 32 + lq) * AST + lr;

    for (int i = 0; i < NC; i++) {
        if (i < NC - 1) { CP_WAIT1(); } else { CP_WAIT0(); }
        __syncthreads();
        const float* buf = sm + (i % 3) * STAGE_F;

        #pragma unroll
        for (int ks = 0; ks < 4; ks++) {
            const int kb = ks * 8;
            uint32_t af[4][4];
            #pragma unroll
            for (int mi = 0; mi < 4; mi++) {
                const float* ap = buf + aoff + mi * (16 * AST) + kb;
                af[mi][0] = __float_as_uint(ap[0]);
                af[mi][1] = __float_as_uint(ap[8 * AST]);
                af[mi][2] = __float_as_uint(ap[4]);
                af[mi][3] = __float_as_uint(ap[8 * AST + 4]);
            }
            uint32_t bf[4][2];
            #pragma unroll
            for (int ni = 0; ni < 4; ni++) {
                const float* bp = buf + boff + ni * (8 * AST) + kb;
                bf[ni][0] = __float_as_uint(bp[0]);
                bf[ni][1] = __float_as_uint(bp[4]);
            }
            #pragma unroll
            for (int mi = 0; mi < 4; mi++)
                #pragma unroll
                for (int ni = 0; ni < 4; ni++)
                    MMA_TF32(acc[mi][ni], af[mi], bf[ni]);
        }
        __syncthreads();
        if (i + 2 < NC) STAGE(i + 2, (i + 2) % 3);
    }
    #undef STAGE

    // epilogue
    #pragma unroll
    for (int mi = 0; mi < 4; mi++) {
        #pragma unroll
        for (int ni = 0; ni < 4; ni++) {
            const int r0 = row0 + wm * 64 + mi * 16 + lq;
            const int c0 = col0 + wn * 32 + ni * 8 + lr * 2;
            float2 v0, v1;
            v0.x = acc[mi][ni][0]; v0.y = acc[mi][ni][1];
            v1.x = acc[mi][ni][2]; v1.y = acc[mi][ni][3];
            if (GELU) {
                v0.x = tf32r(gelu_exact(v0.x)); v0.y = tf32r(gelu_exact(v0.y));
                v1.x = tf32r(gelu_exact(v1.x)); v1.y = tf32r(gelu_exact(v1.y));
            }
            *(float2*)(Ce + (size_t)r0 * N + c0) = v0;
            *(float2*)(Ce + (size_t)(r0 + 8) * N + c0) = v1;
        }
    }
}

// ---------------- Kernel 6: combine ---------------------------------------
__global__ void k_combine(float* __restrict__ out)
{
    const int t = blockIdx.x;
    const int s0 = g_slot[2 * t + 0];
    const int s1 = g_slot[2 * t + 1];
    const float g0 = g_gk[2 * t + 0];
    const float g1 = g_gk[2 * t + 1];
    const float4* y0 = (const float4*)(g_ybuf + (size_t)s0 * DD);
    const float4* y1 = (const float4*)(g_ybuf + (size_t)s1 * DD);
    float4* o = (float4*)(out + (size_t)t * DD);
    const float4 a = y0[threadIdx.x];
    const float4 b = y1[threadIdx.x];
    o[threadIdx.x] = make_float4(g0 * a.x + g1 * b.x,
                                 g0 * a.y + g1 * b.y,
                                 g0 * a.z + g1 * b.z,
                                 g0 * a.w + g1 * b.w);
}

// ---------------- launch ---------------------------------------------------
extern "C" void kernel_launch(void* const* d_in, const int* in_sizes, int n_in,
                              void* d_out, int out_size)
{
    const float* x    = (const float*)d_in[0];  // [B,S,D]
    const float* rmsw = (const float*)d_in[1];  // [D]
    const float* wr   = (const float*)d_in[2];  // [D,E]
    const float* w1   = (const float*)d_in[3];  // [E,D,F]
    const float* w2   = (const float*)d_in[4];  // [E,F,D]
    float* out = (float*)d_out;

    float *xbuf_p, *mid_p, *ybuf_p, *w1t_p, *w2t_p;
    cudaGetSymbolAddress((void**)&xbuf_p, g_xbuf);
    cudaGetSymbolAddress((void**)&mid_p,  g_mid);
    cudaGetSymbolAddress((void**)&ybuf_p, g_ybuf);
    cudaGetSymbolAddress((void**)&w1t_p,  g_w1t);
    cudaGetSymbolAddress((void**)&w2t_p,  g_w2t);

    cudaFuncSetAttribute(k_mmagemm<true>,  cudaFuncAttributeMaxDynamicSharedMemorySize, SMEMSZ);
    cudaFuncSetAttribute(k_mmagemm<false>, cudaFuncAttributeMaxDynamicSharedMemorySize, SMEMSZ);

    // weight transposes (+tf32 rounding): w1 [E,D,F] -> w1t [E,F,D]; w2 [E,F,D] -> w2t [E,D,F]
    k_transpose_round<<<dim3(FD / 32, DD / 32, ED), dim3(32, 8)>>>(w1, w1t_p, DD, FD);
    k_transpose_round<<<dim3(DD / 32, FD / 32, ED), dim3(32, 8)>>>(w2, w2t_p, FD, DD);

    // 1. RMSNorm + router
    k_rms_router<<<TT, 256>>>(x, rmsw, wr);
    // 2. capacity scan
    k_route_scan<<<1, 256>>>();
    // 3. dispatch (tf32-rounded)
    k_dispatch<<<ED * CC, 256>>>();
    // 4. GEMM1 + GeLU: [E] x ( xbuf[C,D] @ w1t[F,D]^T ) -> mid [E,C,F]
    {
        dim3 grid(CC / 128, FD / 128, ED);
        k_mmagemm<true><<<grid, 256, SMEMSZ>>>(xbuf_p, w1t_p, mid_p, FD, DD);
    }
    // 5. GEMM2: [E] x ( mid[C,F] @ w2t[D,F]^T ) -> ybuf [E,C,D]
    {
        dim3 grid(CC / 128, DD / 128, ED);
        k_mmagemm<false><<<grid, 256, SMEMSZ>>>(mid_p, w2t_p, ybuf_p, DD, FD);
    }
    // 6. combine
    k_combine<<<TT, 256>>>(out);
}

// round 4
// speedup vs baseline: 3.3429x; 1.0963x over previous
#include <cuda_runtime.h>
#include <math.h>
#include <stdint.h>

// Problem constants
#define BD   4
#define SD   2048
#define DD   1024
#define FD   4096
#define ED   8
#define KK   2
#define TT   (BD*SD)          // 8192 tokens
#define CC   2048             // capacity per expert
#define NA   (TT*KK)          // 16384 assignments
#define RMS_EPS 1e-6f

// ---------------- scratch (device globals; no allocation allowed) ----------
__device__ float g_tnorm[(size_t)TT * DD];            // 33.5 MB
__device__ float g_xbuf [(size_t)ED * CC * DD];       // 67 MB  (tf32-rounded)
__device__ float g_mid  [(size_t)ED * CC * FD];       // 268 MB (tf32-rounded)
__device__ float g_ybuf [(size_t)ED * CC * DD];       // 67 MB
__device__ float g_w1t  [(size_t)ED * DD * FD];       // 134 MB [E,F,D] tf32-rounded
__device__ float g_w2t  [(size_t)ED * DD * FD];       // 134 MB [E,D,F] tf32-rounded
__device__ int   g_eidx [NA];
__device__ float g_gate [NA];
__device__ int   g_slot [NA];
__device__ float g_gk   [NA];
__device__ int   g_sinv [ED * CC];

// ---------------- helpers ---------------------------------------------------
__device__ __forceinline__ float tf32r(float x) {
    uint32_t r;
    asm("cvt.rna.tf32.f32 %0, %1;" : "=r"(r) : "f"(x));
    return __uint_as_float(r);
}

#define CP_ASYNC16(sm, gp) \
    asm volatile("cp.async.cg.shared.global [%0], [%1], 16;" :: "r"(sm), "l"(gp) : "memory")
#define CP_COMMIT() asm volatile("cp.async.commit_group;" ::: "memory")
#define CP_WAIT1()  asm volatile("cp.async.wait_group 1;" ::: "memory")
#define CP_WAIT0()  asm volatile("cp.async.wait_group 0;" ::: "memory")

__device__ __forceinline__ uint32_t smem_u32(const void* p) {
    uint32_t a;
    asm("{ .reg .u64 t; cvta.to.shared.u64 t, %1; cvt.u32.u64 %0, t; }" : "=r"(a) : "l"(p));
    return a;
}

#define MMA_TF32(d, a, b) \
    asm volatile("mma.sync.aligned.m16n8k8.row.col.f32.tf32.tf32.f32 " \
        "{%0,%1,%2,%3}, {%4,%5,%6,%7}, {%8,%9}, {%0,%1,%2,%3};" \
        : "+f"((d)[0]), "+f"((d)[1]), "+f"((d)[2]), "+f"((d)[3]) \
        : "r"((a)[0]), "r"((a)[1]), "r"((a)[2]), "r"((a)[3]), \
          "r"((b)[0]), "r"((b)[1]))

__device__ __forceinline__ float gelu_exact(float v) {
    return 0.5f * v * (1.f + erff(v * 0.70710678118654752f));
}

// ---------------- Kernel 1: RMSNorm + router + softmax + top-2 ------------
__global__ void k_rms_router(const float* __restrict__ x,
                             const float* __restrict__ rmsw,
                             const float* __restrict__ wr)
{
    const int t = blockIdx.x;
    const int tid = threadIdx.x;             // 256 threads
    const float* xr = x + (size_t)t * DD;

    float ss = 0.f;
    for (int d = tid; d < DD; d += 256) { float v = xr[d]; ss += v * v; }
    __shared__ float s_red[8];
    for (int o = 16; o > 0; o >>= 1) ss += __shfl_down_sync(0xffffffff, ss, o);
    if ((tid & 31) == 0) s_red[tid >> 5] = ss;
    __syncthreads();
    if (tid == 0) {
        float tot = 0.f;
        #pragma unroll
        for (int w = 0; w < 8; w++) tot += s_red[w];
        s_red[0] = rsqrtf(tot / (float)DD + RMS_EPS);
    }
    __syncthreads();
    const float scale = s_red[0];

    float acc[ED];
    #pragma unroll
    for (int e = 0; e < ED; e++) acc[e] = 0.f;
    for (int d = tid; d < DD; d += 256) {
        float h = xr[d] * scale * rmsw[d];
        g_tnorm[(size_t)t * DD + d] = h;
        const float4 w0 = *(const float4*)(wr + (size_t)d * ED);
        const float4 w1 = *(const float4*)(wr + (size_t)d * ED + 4);
        acc[0] += h * w0.x; acc[1] += h * w0.y; acc[2] += h * w0.z; acc[3] += h * w0.w;
        acc[4] += h * w1.x; acc[5] += h * w1.y; acc[6] += h * w1.z; acc[7] += h * w1.w;
    }
    __shared__ float s_r[8][ED];
    #pragma unroll
    for (int e = 0; e < ED; e++) {
        float v = acc[e];
        for (int o = 16; o > 0; o >>= 1) v += __shfl_down_sync(0xffffffff, v, o);
        if ((tid & 31) == 0) s_r[tid >> 5][e] = v;
    }
    __syncthreads();
    __shared__ float s_log[ED];
    if (tid < ED) {
        float v = 0.f;
        #pragma unroll
        for (int w = 0; w < 8; w++) v += s_r[w][tid];
        s_log[tid] = v;
    }
    __syncthreads();
    if (tid == 0) {
        float m = s_log[0];
        #pragma unroll
        for (int e = 1; e < ED; e++) m = fmaxf(m, s_log[e]);
        float p[ED]; float sum = 0.f;
        #pragma unroll
        for (int e = 0; e < ED; e++) { p[e] = __expf(s_log[e] - m); sum += p[e]; }
        const float inv = 1.f / sum;
        #pragma unroll
        for (int e = 0; e < ED; e++) p[e] *= inv;
        int b0 = 0; float v0 = p[0];
        #pragma unroll
        for (int e = 1; e < ED; e++) if (p[e] > v0) { v0 = p[e]; b0 = e; }
        int b1 = -1; float v1 = -1.f;
        #pragma unroll
        for (int e = 0; e < ED; e++) if (e != b0 && p[e] > v1) { v1 = p[e]; b1 = e; }
        g_eidx[2 * t + 0] = b0; g_gate[2 * t + 0] = v0;
        g_eidx[2 * t + 1] = b1; g_gate[2 * t + 1] = v1;
    }
}

// ---------------- Kernel 2: capacity scan (smem-staged, warp scans) --------
__global__ void k_route_scan()
{
    __shared__ uint8_t s_e[NA];              // 16 KB
    __shared__ int s_cnt[256][ED];           // 8 KB
    __shared__ int s_pre[256][ED];           // 8 KB
    const int tid = threadIdx.x;             // 256 threads
    const int wid = tid >> 5, lane = tid & 31;

    for (int i = tid; i < NA; i += 256) s_e[i] = (uint8_t)g_eidx[i];
    for (int i = tid; i < ED * CC; i += 256) g_sinv[i] = -1;
    __syncthreads();

    const int base = tid * (NA / 256);       // 64 per thread
    int cnt[ED];
    #pragma unroll
    for (int e = 0; e < ED; e++) cnt[e] = 0;
    for (int j = 0; j < NA / 256; j++) cnt[s_e[base + j]]++;
    #pragma unroll
    for (int e = 0; e < ED; e++) s_cnt[tid][e] = cnt[e];
    __syncthreads();

    // warp w scans expert w over the 256 thread-counts
    if (wid < ED) {
        int loc[8]; int sum = 0;
        #pragma unroll
        for (int j = 0; j < 8; j++) { loc[j] = sum; sum += s_cnt[lane * 8 + j][wid]; }
        int v = sum;
        #pragma unroll
        for (int o = 1; o < 32; o <<= 1) {
            int tv = __shfl_up_sync(0xffffffff, v, o);
            if (lane >= o) v += tv;
        }
        const int excl = v - sum;
        #pragma unroll
        for (int j = 0; j < 8; j++) s_pre[lane * 8 + j][wid] = excl + loc[j];
    }
    __syncthreads();

    int pos[ED];
    #pragma unroll
    for (int e = 0; e < ED; e++) pos[e] = s_pre[tid][e];
    for (int j = 0; j < NA / 256; j++) {
        const int a = base + j;
        const int e = s_e[a];
        const int p = pos[e]++;
        const bool keep = (p < CC);
        const int sl = e * CC + (p < CC ? p : CC - 1);
        g_slot[a] = sl;
        g_gk[a] = keep ? g_gate[a] : 0.f;
        if (keep) g_sinv[sl] = a;
    }
}

// ---------------- Kernel 3: dispatch gather (+ tf32 round) -----------------
__global__ void k_dispatch()
{
    const int s = blockIdx.x;                // E*C slots
    const int a = g_sinv[s];
    float4* dst = (float4*)(g_xbuf + (size_t)s * DD);
    if (a < 0) {
        dst[threadIdx.x] = make_float4(0.f, 0.f, 0.f, 0.f);
    } else {
        const int tok = a >> 1;
        const float4* src = (const float4*)(g_tnorm + (size_t)tok * DD);
        float4 v = src[threadIdx.x];
        v.x = tf32r(v.x); v.y = tf32r(v.y); v.z = tf32r(v.z); v.w = tf32r(v.w);
        dst[threadIdx.x] = v;
    }
}

// ---------------- Kernel 4: weight transpose + tf32 round ------------------
// src [e][R][C] -> dst [e][C][R]
__global__ void k_transpose_round(const float* __restrict__ src,
                                  float* __restrict__ dst, int R, int C)
{
    __shared__ float t[32][33];
    const int e = blockIdx.z;
    const float* s = src + (size_t)e * R * C;
    float* d = dst + (size_t)e * R * C;
    const int x = blockIdx.x * 32 + threadIdx.x;
    const int y0 = blockIdx.y * 32;
    #pragma unroll
    for (int j = 0; j < 4; j++)
        t[threadIdx.y + 8 * j][threadIdx.x] = s[(size_t)(y0 + threadIdx.y + 8 * j) * C + x];
    __syncthreads();
    const int x2 = y0 + threadIdx.x;
    const int y2 = blockIdx.x * 32;
    #pragma unroll
    for (int j = 0; j < 4; j++)
        d[(size_t)(y2 + threadIdx.y + 8 * j) * R + x2] = tf32r(t[threadIdx.x][threadIdx.y + 8 * j]);
}

// ---------------- Kernel 5: tf32 mma.sync GEMM -----------------------------
// A: [E, CC, Kd] K-major. B: [E, N, Kd] K-major. C[m][n] = sum_k A[m][k]*B[n][k].
// CTA tile 128x256, BK=32, 3-stage cp.async, 8 warps (2x4) of 64x64.
#define BKC 32
#define AST 36                          // padded row stride (floats)
#define ASZ (128 * AST)                 // A floats per stage
#define STAGE_F ((128 + 256) * AST)     // floats per stage
#define STAGE_B (STAGE_F * 4)
#define SMEMSZ (3 * STAGE_B)

template<bool GELU>
__global__ void __launch_bounds__(256, 1)
k_mmagemm(const float* __restrict__ A, const float* __restrict__ B,
          float* __restrict__ C, int N, int Kd)
{
    extern __shared__ float sm[];
    const int tid = threadIdx.x;
    const int wid = tid >> 5;
    const int lane = tid & 31;
    const int lq = lane >> 2;       // 0..7
    const int lr = lane & 3;        // 0..3
    const int wm = wid >> 2;        // 0..1 (64-row half)
    const int wn = wid & 3;         // 0..3 (64-col quarter)

    const int e = blockIdx.z;
    const int row0 = blockIdx.x * 128;
    const int col0 = blockIdx.y * 256;

    const float* Ag = A + (size_t)e * CC * Kd + (size_t)row0 * Kd;
    const float* Bg = B + (size_t)e * N * Kd + (size_t)col0 * Kd;
    float* Ce = C + (size_t)e * CC * N;

    // staging: vector v (0..3071): row = v>>3, c4 = v&7; 256 threads, 12 passes
    const uint32_t sbase = smem_u32(sm);
    const int srow = tid >> 3, sc4 = tid & 7;
    const float* gA0 = Ag + (size_t)srow * Kd + sc4 * 4;
    const float* gB0 = Bg + (size_t)srow * Kd + sc4 * 4;
    const uint32_t sA0 = sbase + (uint32_t)(srow * AST + sc4 * 4) * 4;
    const uint32_t sB0 = sbase + (uint32_t)(ASZ + srow * AST + sc4 * 4) * 4;
    const size_t gstep = (size_t)32 * Kd;       // 32 rows per 256-thread pass
    const uint32_t sstep = 32 * AST * 4;

    #define STAGE(chunk, buf) do { \
        const uint32_t _o = (uint32_t)(buf) * STAGE_B; \
        const int _k = (chunk) * BKC; \
        _Pragma("unroll") \
        for (int _j = 0; _j < 4; _j++) CP_ASYNC16(sA0 + _o + _j * sstep, gA0 + _k + _j * gstep); \
        _Pragma("unroll") \
        for (int _j = 0; _j < 8; _j++) CP_ASYNC16(sB0 + _o + _j * sstep, gB0 + _k + _j * gstep); \
        CP_COMMIT(); \
    } while (0)

    const int NC = Kd / BKC;
    STAGE(0, 0);
    STAGE(1, 1);

    float acc[4][8][4];
    #pragma unroll
    for (int mi = 0; mi < 4; mi++)
        #pragma unroll
        for (int ni = 0; ni < 8; ni++)
            #pragma unroll
            for (int q = 0; q < 4; q++) acc[mi][ni][q] = 0.f;

    const int aoff = (wm * 64 + lq) * AST + lr;
    const int boff = ASZ + (wn * 64 + lq) * AST + lr;

    for (int i = 0; i < NC; i++) {
        if (i < NC - 1) { CP_WAIT1(); } else { CP_WAIT0(); }
        __syncthreads();
        if (i + 2 < NC) STAGE(i + 2, (i + 2) % 3);   // overlap copy with compute
        const float* buf = sm + (i % 3) * STAGE_F;

        #pragma unroll
        for (int ks = 0; ks < 4; ks++) {
            const int kb = ks * 8;
            uint32_t af[4][4];
            #pragma unroll
            for (int mi = 0; mi < 4; mi++) {
                const float* ap = buf + aoff + mi * (16 * AST) + kb;
                af[mi][0] = __float_as_uint(ap[0]);
                af[mi][1] = __float_as_uint(ap[8 * AST]);
                af[mi][2] = __float_as_uint(ap[4]);
                af[mi][3] = __float_as_uint(ap[8 * AST + 4]);
            }
            uint32_t bf[8][2];
            #pragma unroll
            for (int ni = 0; ni < 8; ni++) {
                const float* bp = buf + boff + ni * (8 * AST) + kb;
                bf[ni][0] = __float_as_uint(bp[0]);
                bf[ni][1] = __float_as_uint(bp[4]);
            }
            #pragma unroll
            for (int mi = 0; mi < 4; mi++)
                #pragma unroll
                for (int ni = 0; ni < 8; ni++)
                    MMA_TF32(acc[mi][ni], af[mi], bf[ni]);
        }
    }
    #undef STAGE

    // epilogue
    #pragma unroll
    for (int mi = 0; mi < 4; mi++) {
        #pragma unroll
        for (int ni = 0; ni < 8; ni++) {
            const int r0 = row0 + wm * 64 + mi * 16 + lq;
            const int c0 = col0 + wn * 64 + ni * 8 + lr * 2;
            float2 v0, v1;
            v0.x = acc[mi][ni][0]; v0.y = acc[mi][ni][1];
            v1.x = acc[mi][ni][2]; v1.y = acc[mi][ni][3];
            if (GELU) {
                v0.x = tf32r(gelu_exact(v0.x)); v0.y = tf32r(gelu_exact(v0.y));
                v1.x = tf32r(gelu_exact(v1.x)); v1.y = tf32r(gelu_exact(v1.y));
            }
            *(float2*)(Ce + (size_t)r0 * N + c0) = v0;
            *(float2*)(Ce + (size_t)(r0 + 8) * N + c0) = v1;
        }
    }
}

// ---------------- Kernel 6: combine ---------------------------------------
__global__ void k_combine(float* __restrict__ out)
{
    const int t = blockIdx.x;
    const int s0 = g_slot[2 * t + 0];
    const int s1 = g_slot[2 * t + 1];
    const float g0 = g_gk[2 * t + 0];
    const float g1 = g_gk[2 * t + 1];
    const float4* y0 = (const float4*)(g_ybuf + (size_t)s0 * DD);
    const float4* y1 = (const float4*)(g_ybuf + (size_t)s1 * DD);
    float4* o = (float4*)(out + (size_t)t * DD);
    const float4 a = y0[threadIdx.x];
    const float4 b = y1[threadIdx.x];
    o[threadIdx.x] = make_float4(g0 * a.x + g1 * b.x,
                                 g0 * a.y + g1 * b.y,
                                 g0 * a.z + g1 * b.z,
                                 g0 * a.w + g1 * b.w);
}

// ---------------- launch ---------------------------------------------------
extern "C" void kernel_launch(void* const* d_in, const int* in_sizes, int n_in,
                              void* d_out, int out_size)
{
    const float* x    = (const float*)d_in[0];  // [B,S,D]
    const float* rmsw = (const float*)d_in[1];  // [D]
    const float* wr   = (const float*)d_in[2];  // [D,E]
    const float* w1   = (const float*)d_in[3];  // [E,D,F]
    const float* w2   = (const float*)d_in[4];  // [E,F,D]
    float* out = (float*)d_out;

    float *xbuf_p, *mid_p, *ybuf_p, *w1t_p, *w2t_p;
    cudaGetSymbolAddress((void**)&xbuf_p, g_xbuf);
    cudaGetSymbolAddress((void**)&mid_p,  g_mid);
    cudaGetSymbolAddress((void**)&ybuf_p, g_ybuf);
    cudaGetSymbolAddress((void**)&w1t_p,  g_w1t);
    cudaGetSymbolAddress((void**)&w2t_p,  g_w2t);

    cudaFuncSetAttribute(k_mmagemm<true>,  cudaFuncAttributeMaxDynamicSharedMemorySize, SMEMSZ);
    cudaFuncSetAttribute(k_mmagemm<false>, cudaFuncAttributeMaxDynamicSharedMemorySize, SMEMSZ);

    // weight transposes (+tf32 rounding): w1 [E,D,F] -> w1t [E,F,D]; w2 [E,F,D] -> w2t [E,D,F]
    k_transpose_round<<<dim3(FD / 32, DD / 32, ED), dim3(32, 8)>>>(w1, w1t_p, DD, FD);
    k_transpose_round<<<dim3(DD / 32, FD / 32, ED), dim3(32, 8)>>>(w2, w2t_p, FD, DD);

    // 1. RMSNorm + router
    k_rms_router<<<TT, 256>>>(x, rmsw, wr);
    // 2. capacity scan
    k_route_scan<<<1, 256>>>();
    // 3. dispatch (tf32-rounded)
    k_dispatch<<<ED * CC, 256>>>();
    // 4. GEMM1 + GeLU: [E] x ( xbuf[C,D] @ w1t[F,D]^T ) -> mid [E,C,F]
    {
        dim3 grid(CC / 128, FD / 256, ED);
        k_mmagemm<true><<<grid, 256, SMEMSZ>>>(xbuf_p, w1t_p, mid_p, FD, DD);
    }
    // 5. GEMM2: [E] x ( mid[C,F] @ w2t[D,F]^T ) -> ybuf [E,C,D]
    {
        dim3 grid(CC / 128, DD / 256, ED);
        k_mmagemm<false><<<grid, 256, SMEMSZ>>>(mid_p, w2t_p, ybuf_p, DD, FD);
    }
    // 6. combine
    k_combine<<<TT, 256>>>(out);
}